// round 1
// baseline (speedup 1.0000x reference)
#include <cuda_runtime.h>
#include <math.h>

#define B_ 32
#define T_ 64
#define N_ 32
#define D_ 128
#define E_ 8
#define K_ 2

// gating results passed between kernels
__device__ int   d_eidx[B_][K_];
__device__ float d_gateg[B_][K_];

// ---------------------------------------------------------------------------
// Kernel 1: noisy-top-k gating (eval mode, no noise)
// logits[b] = mean_{t,n}(x[b]) @ Wg ; top-2 ; softmax over top values
// ---------------------------------------------------------------------------
__global__ void gate_kernel(const float* __restrict__ x,
                            const float* __restrict__ Wg) {
    const int b   = blockIdx.x;
    const int tid = threadIdx.x;  // 128 threads
    __shared__ float smean[D_];
    __shared__ float slog[E_];

    const float* xb = x + (size_t)b * T_ * N_ * D_;
    float s = 0.f;
    for (int i = 0; i < T_ * N_; ++i) s += xb[(size_t)i * D_ + tid];
    smean[tid] = s * (1.0f / (float)(T_ * N_));
    __syncthreads();

    if (tid < E_) {
        float l = 0.f;
        for (int d = 0; d < D_; ++d) l += smean[d] * Wg[d * E_ + tid];
        slog[tid] = l;
    }
    __syncthreads();

    if (tid == 0) {
        // top-2 (strict > keeps lowest index on ties, matching lax.top_k)
        int i0 = 0; float v0 = slog[0];
        for (int e = 1; e < E_; ++e) if (slog[e] > v0) { v0 = slog[e]; i0 = e; }
        int i1 = -1; float v1 = -3.0e38f;
        for (int e = 0; e < E_; ++e) if (e != i0 && slog[e] > v1) { v1 = slog[e]; i1 = e; }
        const float e1  = expf(v1 - v0);
        const float inv = 1.0f / (1.0f + e1);
        d_eidx[b][0]  = i0; d_eidx[b][1]  = i1;
        d_gateg[b][0] = inv; d_gateg[b][1] = e1 * inv;
    }
}

// ---------------------------------------------------------------------------
// Kernel 2: one CTA per (b, n). 256 threads.
// SMEM: xs[64][128] | kst[128][65] (later reused as o[64][128]) |
//       vs[64][128] | att[128][64]
// Pipeline per selected expert:
//   GEMM1: k = xs@Wd0+bd0 (stored transposed), v = xs@Wd1+bd1
//   attGEMM: att[h*64+qt][kt] = (q.k)/8
//   softmax over kt (warp-cooperative)
//   oGEMM: o[t][c] = att @ v     (written into kst region)
//   GEMM2: o1 = relu(o@Ws0+bs0) -> vs
//   GEMM3: out = o1@Ws1+bs1 ; accv += gate * exp(out)   (registers)
// Final: out = log(accv)  (EPS guard)
// ---------------------------------------------------------------------------
__global__ __launch_bounds__(256, 1)
void moe_kernel(const float* __restrict__ x,
                const float* __restrict__ Wd,
                const float* __restrict__ bd,
                const float* __restrict__ Ws,
                const float* __restrict__ bs,
                float* __restrict__ out) {
    extern __shared__ float sm[];
    float* xs  = sm;                   // 8192 floats
    float* kst = sm + 8192;            // 8320 floats ([128][65]); reused as o[64][128]
    float* vs  = sm + 8192 + 8320;     // 8192 floats
    float* att = vs + 8192;            // 8192 floats ([128][64])

    const int n   = blockIdx.x;
    const int b   = blockIdx.y;
    const int tid = threadIdx.x;
    const int lane = tid & 31;
    const int wid  = tid >> 5;

    // ---- load x slab [T][D] (coalesced float4) ----
    {
        const float4* xg  = (const float4*)(x + ((size_t)b * T_ * N_ + n) * D_);
        float4*       xs4 = (float4*)xs;
        #pragma unroll
        for (int i = tid; i < T_ * D_ / 4; i += 256) {
            const int t = i >> 5;   // 32 float4 per row
            const int c = i & 31;
            xs4[t * 32 + c] = xg[(size_t)t * (N_ * D_ / 4) + c];
        }
    }

    const int dc = tid & 127;   // output column for GEMM-shaped phases
    const int tb = tid >> 7;    // 0/1: row parity

    float accv[32];
    #pragma unroll
    for (int j = 0; j < 32; ++j) accv[j] = 0.f;

    __syncthreads();

    for (int slot = 0; slot < K_; ++slot) {
        const int   e = d_eidx[b][slot];
        const float g = d_gateg[b][slot];
        const float* W0 = Wd + ((size_t)(e * 2 + 0) * N_ + n) * D_ * D_;
        const float* W1 = Wd + ((size_t)(e * 2 + 1) * N_ + n) * D_ * D_;
        const float* b0 = bd + ((size_t)(e * 2 + 0) * N_ + n) * D_;
        const float* b1 = bd + ((size_t)(e * 2 + 1) * N_ + n) * D_;

        // ---- GEMM1: k (transposed store), v ----
        {
            float ak[32], av[32];
            const float bk = b0[dc], bv = b1[dc];
            #pragma unroll
            for (int j = 0; j < 32; ++j) { ak[j] = bk; av[j] = bv; }
            for (int d = 0; d < D_; d += 2) {
                const float w0a = W0[d * D_ + dc], w0b = W0[(d + 1) * D_ + dc];
                const float w1a = W1[d * D_ + dc], w1b = W1[(d + 1) * D_ + dc];
                #pragma unroll
                for (int j = 0; j < 32; ++j) {
                    const float2 xv = *(const float2*)&xs[(tb + 2 * j) * D_ + d];
                    ak[j] = fmaf(xv.x, w0a, ak[j]); ak[j] = fmaf(xv.y, w0b, ak[j]);
                    av[j] = fmaf(xv.x, w1a, av[j]); av[j] = fmaf(xv.y, w1b, av[j]);
                }
            }
            #pragma unroll
            for (int j = 0; j < 32; ++j) {
                const int t = tb + 2 * j;
                kst[dc * 65 + t] = ak[j];      // [dd=dc][kt=t], pad 65: conflict-free
                vs[t * D_ + dc]  = av[j];
            }
        }
        __syncthreads();

        // ---- attention scores: att[hq][kt] = (q . k)/8 ----
        {
            const int kt = tid & 63;
            const int rb = tid >> 6;  // 0..3
            float aa[32];
            #pragma unroll
            for (int j = 0; j < 32; ++j) aa[j] = 0.f;
            for (int d = 0; d < 64; ++d) {
                const float k0 = kst[d * 65 + kt];          // head 0, lanes: kt contiguous
                const float k1 = kst[(64 + d) * 65 + kt];   // head 1
                #pragma unroll
                for (int i = 0; i < 16; ++i) {
                    const int qt = rb + 4 * i;
                    aa[i]      = fmaf(xs[qt * D_ + d],      k0, aa[i]);       // broadcast
                    aa[16 + i] = fmaf(xs[qt * D_ + 64 + d], k1, aa[16 + i]);  // broadcast
                }
            }
            #pragma unroll
            for (int i = 0; i < 16; ++i) {
                att[(rb + 4 * i) * 64 + kt]        = aa[i]      * 0.125f;
                att[(64 + rb + 4 * i) * 64 + kt]   = aa[16 + i] * 0.125f;
            }
        }
        __syncthreads();

        // ---- softmax over kt, warp-cooperative (warp wid: rows wid*16..+15) ----
        for (int r = wid * 16; r < wid * 16 + 16; ++r) {
            const float a0 = att[r * 64 + lane];
            const float a1 = att[r * 64 + 32 + lane];
            float m = fmaxf(a0, a1);
            #pragma unroll
            for (int o = 16; o > 0; o >>= 1) m = fmaxf(m, __shfl_xor_sync(0xffffffffu, m, o));
            const float e0 = expf(a0 - m);
            const float e1x = expf(a1 - m);
            float s = e0 + e1x;
            #pragma unroll
            for (int o = 16; o > 0; o >>= 1) s += __shfl_xor_sync(0xffffffffu, s, o);
            const float inv = 1.0f / s;
            att[r * 64 + lane]      = e0 * inv;
            att[r * 64 + 32 + lane] = e1x * inv;
        }
        __syncthreads();

        // ---- oGEMM: o[t][c] = sum_kt att[hh*64+t][kt] * v[kt][c]  -> kst region ----
        {
            const int hh = dc >> 6;
            float ao[32];
            #pragma unroll
            for (int j = 0; j < 32; ++j) ao[j] = 0.f;
            for (int kt = 0; kt < 64; ++kt) {
                const float vv = vs[kt * D_ + dc];   // lanes: dc contiguous
                #pragma unroll
                for (int j = 0; j < 32; ++j) {
                    const int t = tb + 2 * j;
                    ao[j] = fmaf(att[(hh * 64 + t) * 64 + kt], vv, ao[j]);  // broadcast
                }
            }
            #pragma unroll
            for (int j = 0; j < 32; ++j) kst[(tb + 2 * j) * D_ + dc] = ao[j];
        }
        __syncthreads();

        const float* Wsh0 = Ws + (size_t)(e * 2 + 0) * D_ * D_;
        const float* Wsh1 = Ws + (size_t)(e * 2 + 1) * D_ * D_;
        const float* bsh0 = bs + (e * 2 + 0) * D_;
        const float* bsh1 = bs + (e * 2 + 1) * D_;

        // ---- GEMM2: o1 = relu(o @ Ws0 + bs0) -> vs ----
        {
            float a2[32];
            const float bb = bsh0[dc];
            #pragma unroll
            for (int j = 0; j < 32; ++j) a2[j] = bb;
            for (int d = 0; d < D_; d += 2) {
                const float wa = Wsh0[d * D_ + dc], wb = Wsh0[(d + 1) * D_ + dc];
                #pragma unroll
                for (int j = 0; j < 32; ++j) {
                    const float2 ov = *(const float2*)&kst[(tb + 2 * j) * D_ + d];
                    a2[j] = fmaf(ov.x, wa, a2[j]); a2[j] = fmaf(ov.y, wb, a2[j]);
                }
            }
            #pragma unroll
            for (int j = 0; j < 32; ++j)
                vs[(tb + 2 * j) * D_ + dc] = fmaxf(a2[j], 0.f);
        }
        __syncthreads();

        // ---- GEMM3: out = o1 @ Ws1 + bs1 ; accumulate gate*exp ----
        {
            float a3[32];
            const float bb = bsh1[dc];
            #pragma unroll
            for (int j = 0; j < 32; ++j) a3[j] = bb;
            for (int d = 0; d < D_; d += 2) {
                const float wa = Wsh1[d * D_ + dc], wb = Wsh1[(d + 1) * D_ + dc];
                #pragma unroll
                for (int j = 0; j < 32; ++j) {
                    const float2 ov = *(const float2*)&vs[(tb + 2 * j) * D_ + d];
                    a3[j] = fmaf(ov.x, wa, a3[j]); a3[j] = fmaf(ov.y, wb, a3[j]);
                }
            }
            #pragma unroll
            for (int j = 0; j < 32; ++j) accv[j] += g * expf(a3[j]);
        }
        __syncthreads();  // before next expert overwrites kst/vs/att
    }

    // ---- combine epilogue: log(sum_e g*exp(out_e)), EPS guard ----
    const float EPSF = 2.2204460492503131e-16f;
    #pragma unroll
    for (int j = 0; j < 32; ++j) {
        const int t = tb + 2 * j;
        float a = accv[j];
        if (a == 0.f) a = EPSF;
        out[(((size_t)b * T_ + t) * N_ + n) * D_ + dc] = logf(a);
    }
}

// ---------------------------------------------------------------------------
// launcher
// ---------------------------------------------------------------------------
extern "C" void kernel_launch(void* const* d_in, const int* in_sizes, int n_in,
                              void* d_out, int out_size) {
    const float* x  = (const float*)d_in[0];
    const float* Wg = (const float*)d_in[1];
    const float* Wd = (const float*)d_in[2];
    const float* bd = (const float*)d_in[3];
    const float* Ws = (const float*)d_in[4];
    const float* bs = (const float*)d_in[5];
    float* out = (float*)d_out;

    const int smem_bytes = (8192 + 8320 + 8192 + 8192) * (int)sizeof(float); // 131584
    cudaFuncSetAttribute(moe_kernel, cudaFuncAttributeMaxDynamicSharedMemorySize, smem_bytes);

    gate_kernel<<<B_, 128>>>(x, Wg);
    dim3 grid(N_, B_);
    moe_kernel<<<grid, 256, smem_bytes>>>(x, Wd, bd, Ws, bs, out);
}

// round 2
// speedup vs baseline: 1.3013x; 1.3013x over previous
#include <cuda_runtime.h>
#include <math.h>

#define B_ 32
#define T_ 64
#define N_ 32
#define D_ 128
#define E_ 8
#define K_ 2
#define XT 66    // stride for [feature][time] tiles (64 + pad, even for LDS.64)
#define AT 130   // stride for att_t [kt][row] tile (128 + pad, even)

typedef unsigned long long u64;

__device__ int   d_eidx[B_][K_];
__device__ float d_gateg[B_][K_];

// ---- f32x2 packed-math helpers (FFMA2 reachable only via PTX) ----
__device__ __forceinline__ u64 f2fma(u64 a, u64 b, u64 c) {
    u64 d; asm("fma.rn.f32x2 %0, %1, %2, %3;" : "=l"(d) : "l"(a), "l"(b), "l"(c)); return d;
}
__device__ __forceinline__ u64 f2mul(u64 a, u64 b) {
    u64 d; asm("mul.rn.f32x2 %0, %1, %2;" : "=l"(d) : "l"(a), "l"(b)); return d;
}
__device__ __forceinline__ u64 fpack(float lo, float hi) {
    u64 d; asm("mov.b64 %0, {%1, %2};" : "=l"(d) : "f"(lo), "f"(hi)); return d;
}
__device__ __forceinline__ u64 fdup(float v) { return fpack(v, v); }
__device__ __forceinline__ float2 funpack(u64 v) {
    float2 r; asm("mov.b64 {%0, %1}, %2;" : "=f"(r.x), "=f"(r.y) : "l"(v)); return r;
}

// ---------------------------------------------------------------------------
// Kernel 1: gating (eval mode)
// ---------------------------------------------------------------------------
__global__ void gate_kernel(const float* __restrict__ x,
                            const float* __restrict__ Wg) {
    const int b   = blockIdx.x;
    const int tid = threadIdx.x;  // 128 threads
    __shared__ float smean[D_];
    __shared__ float slog[E_];

    const float* xb = x + (size_t)b * T_ * N_ * D_;
    float s = 0.f;
    for (int i = 0; i < T_ * N_; ++i) s += xb[(size_t)i * D_ + tid];
    smean[tid] = s * (1.0f / (float)(T_ * N_));
    __syncthreads();

    if (tid < E_) {
        float l = 0.f;
        for (int d = 0; d < D_; ++d) l += smean[d] * Wg[d * E_ + tid];
        slog[tid] = l;
    }
    __syncthreads();

    if (tid == 0) {
        int i0 = 0; float v0 = slog[0];
        for (int e = 1; e < E_; ++e) if (slog[e] > v0) { v0 = slog[e]; i0 = e; }
        int i1 = -1; float v1 = -3.0e38f;
        for (int e = 0; e < E_; ++e) if (e != i0 && slog[e] > v1) { v1 = slog[e]; i1 = e; }
        const float e1  = expf(v1 - v0);
        const float inv = 1.0f / (1.0f + e1);
        d_eidx[b][0]  = i0; d_eidx[b][1]  = i1;
        d_gateg[b][0] = inv; d_gateg[b][1] = e1 * inv;
    }
}

// ---------------------------------------------------------------------------
// Kernel 2: one CTA per (b, n). 256 threads. All big GEMM phases use f32x2.
// SMEM: xs_t[128][66] | kst[128][66] (k_t then o_t) | vs[64][128] |
//       ar (att_t[64][130], then o1_t[128][66])  -> 33536 floats = 131 KB
// ---------------------------------------------------------------------------
__global__ __launch_bounds__(256, 1)
void moe_kernel(const float* __restrict__ x,
                const float* __restrict__ Wd,
                const float* __restrict__ bd,
                const float* __restrict__ Ws,
                const float* __restrict__ bs,
                float* __restrict__ out) {
    extern __shared__ float sm[];
    float* xs  = sm;                 // 8448 floats  [d][t] stride 66
    float* kst = sm + 8448;          // 8448 floats  [feat][t] stride 66
    float* vs  = sm + 16896;         // 8192 floats  [t][feat]
    float* ar  = sm + 25088;         // 8448 floats  att_t[kt][row]=130 / o1_t stride 66

    const int n    = blockIdx.x;
    const int b    = blockIdx.y;
    const int tid  = threadIdx.x;
    const int lane = tid & 31;
    const int wid  = tid >> 5;

    // ---- load x slab [T][D] coalesced, store transposed xs_t[d][t] ----
    {
        const float4* xg = (const float4*)(x + ((size_t)b * T_ * N_ + n) * D_);
        for (int i = tid; i < T_ * D_ / 4; i += 256) {
            const int t  = i >> 5;
            const int c4 = i & 31;
            float4 v = xg[(size_t)t * (N_ * D_ / 4) + c4];
            const int d0 = c4 * 4;
            xs[(d0 + 0) * XT + t] = v.x;
            xs[(d0 + 1) * XT + t] = v.y;
            xs[(d0 + 2) * XT + t] = v.z;
            xs[(d0 + 3) * XT + t] = v.w;
        }
    }

    // GEMM thread mapping: column-pair cp, row-group rg (16 rows = 8 pairs)
    const int cp = tid & 63;
    const int rg = tid >> 6;
    const int c0 = cp * 2;
    const int tb = rg * 16;

    float accv[8][2][2];  // [row-pair][col][row-in-pair]
    #pragma unroll
    for (int p = 0; p < 8; ++p)
        for (int q = 0; q < 2; ++q) { accv[p][q][0] = 0.f; accv[p][q][1] = 0.f; }

    __syncthreads();

    for (int slot = 0; slot < K_; ++slot) {
        const int   e = d_eidx[b][slot];
        const float g = d_gateg[b][slot];
        const float* W0 = Wd + ((size_t)(e * 2 + 0) * N_ + n) * D_ * D_;
        const float* W1 = Wd + ((size_t)(e * 2 + 1) * N_ + n) * D_ * D_;
        const float* b0 = bd + ((size_t)(e * 2 + 0) * N_ + n) * D_;
        const float* b1 = bd + ((size_t)(e * 2 + 1) * N_ + n) * D_;

        // ---- GEMM1: k = x@W0+b0 (store transposed), v = x@W1+b1 ----
        {
            u64 ak[8][2], av2[8][2];
            const float2 bk = *(const float2*)&b0[c0];
            const float2 bv = *(const float2*)&b1[c0];
            #pragma unroll
            for (int p = 0; p < 8; ++p) {
                ak[p][0] = fdup(bk.x);  ak[p][1] = fdup(bk.y);
                av2[p][0] = fdup(bv.x); av2[p][1] = fdup(bv.y);
            }
            u64 w0n = *(const u64*)&W0[c0];
            u64 w1n = *(const u64*)&W1[c0];
            #pragma unroll 2
            for (int d = 0; d < D_; ++d) {
                const float2 w0 = funpack(w0n);
                const float2 w1 = funpack(w1n);
                if (d + 1 < D_) {
                    w0n = *(const u64*)&W0[(d + 1) * D_ + c0];
                    w1n = *(const u64*)&W1[(d + 1) * D_ + c0];
                }
                const u64 w0x = fdup(w0.x), w0y = fdup(w0.y);
                const u64 w1x = fdup(w1.x), w1y = fdup(w1.y);
                #pragma unroll
                for (int p = 0; p < 8; ++p) {
                    const u64 xv = *(const u64*)&xs[d * XT + tb + 2 * p];
                    ak[p][0]  = f2fma(xv, w0x, ak[p][0]);
                    ak[p][1]  = f2fma(xv, w0y, ak[p][1]);
                    av2[p][0] = f2fma(xv, w1x, av2[p][0]);
                    av2[p][1] = f2fma(xv, w1y, av2[p][1]);
                }
            }
            #pragma unroll
            for (int p = 0; p < 8; ++p) {
                *(u64*)&kst[(c0 + 0) * XT + tb + 2 * p] = ak[p][0];
                *(u64*)&kst[(c0 + 1) * XT + tb + 2 * p] = ak[p][1];
                const float2 u0 = funpack(av2[p][0]);
                const float2 u1 = funpack(av2[p][1]);
                vs[(tb + 2 * p)     * D_ + c0]     = u0.x;
                vs[(tb + 2 * p + 1) * D_ + c0]     = u0.y;
                vs[(tb + 2 * p)     * D_ + c0 + 1] = u1.x;
                vs[(tb + 2 * p + 1) * D_ + c0 + 1] = u1.y;
            }
        }
        __syncthreads();

        // ---- attention scores: att_t[kt][h*64+qt] = (q.k)/8 ----
        // thread: kt = cp, q-rows = tb..tb+15 (both heads)
        {
            u64 aa0[8], aa1[8];
            #pragma unroll
            for (int p = 0; p < 8; ++p) { aa0[p] = 0ull; aa1[p] = 0ull; }
            #pragma unroll 2
            for (int d = 0; d < 64; ++d) {
                const u64 k0 = fdup(kst[d * XT + cp]);
                const u64 k1 = fdup(kst[(64 + d) * XT + cp]);
                #pragma unroll
                for (int p = 0; p < 8; ++p) {
                    const u64 x0 = *(const u64*)&xs[d * XT + tb + 2 * p];
                    const u64 x1 = *(const u64*)&xs[(64 + d) * XT + tb + 2 * p];
                    aa0[p] = f2fma(x0, k0, aa0[p]);
                    aa1[p] = f2fma(x1, k1, aa1[p]);
                }
            }
            const u64 sc = fdup(0.125f);
            #pragma unroll
            for (int p = 0; p < 8; ++p) {
                *(u64*)&ar[cp * AT + tb + 2 * p]      = f2mul(aa0[p], sc);
                *(u64*)&ar[cp * AT + 64 + tb + 2 * p] = f2mul(aa1[p], sc);
            }
        }
        __syncthreads();

        // ---- softmax over kt (rows of att_t columns) ----
        for (int r = wid * 16; r < wid * 16 + 16; ++r) {
            const float a0 = ar[lane * AT + r];
            const float a1 = ar[(lane + 32) * AT + r];
            float m = fmaxf(a0, a1);
            #pragma unroll
            for (int o = 16; o > 0; o >>= 1) m = fmaxf(m, __shfl_xor_sync(0xffffffffu, m, o));
            const float e0 = expf(a0 - m);
            const float e1x = expf(a1 - m);
            float s = e0 + e1x;
            #pragma unroll
            for (int o = 16; o > 0; o >>= 1) s += __shfl_xor_sync(0xffffffffu, s, o);
            const float inv = 1.0f / s;
            ar[lane * AT + r]        = e0 * inv;
            ar[(lane + 32) * AT + r] = e1x * inv;
        }
        __syncthreads();

        // ---- oGEMM: o_t[dc][t] = sum_kt att_t[kt][hh*64+t] * v[kt][dc] ----
        {
            const int dc = tid & 127;
            const int tq = (tid >> 7) * 32;   // 32 rows = 16 pairs
            const int hh = dc >> 6;
            u64 ao[16];
            #pragma unroll
            for (int p = 0; p < 16; ++p) ao[p] = 0ull;
            #pragma unroll 2
            for (int ktt = 0; ktt < 64; ++ktt) {
                const u64 vv = fdup(vs[ktt * D_ + dc]);
                #pragma unroll
                for (int p = 0; p < 16; ++p) {
                    const u64 at = *(const u64*)&ar[ktt * AT + hh * 64 + tq + 2 * p];
                    ao[p] = f2fma(at, vv, ao[p]);
                }
            }
            #pragma unroll
            for (int p = 0; p < 16; ++p)
                *(u64*)&kst[dc * XT + tq + 2 * p] = ao[p];
        }
        __syncthreads();

        const float* Wsh0 = Ws + (size_t)(e * 2 + 0) * D_ * D_;
        const float* Wsh1 = Ws + (size_t)(e * 2 + 1) * D_ * D_;
        const float* bsh0 = bs + (e * 2 + 0) * D_;
        const float* bsh1 = bs + (e * 2 + 1) * D_;

        // ---- GEMM2: o1 = relu(o @ Ws0 + bs0) -> ar as o1_t ----
        {
            u64 a2[8][2];
            const float2 bb = *(const float2*)&bsh0[c0];
            #pragma unroll
            for (int p = 0; p < 8; ++p) { a2[p][0] = fdup(bb.x); a2[p][1] = fdup(bb.y); }
            u64 wn = *(const u64*)&Wsh0[c0];
            #pragma unroll 2
            for (int d = 0; d < D_; ++d) {
                const float2 w = funpack(wn);
                if (d + 1 < D_) wn = *(const u64*)&Wsh0[(d + 1) * D_ + c0];
                const u64 wx = fdup(w.x), wy = fdup(w.y);
                #pragma unroll
                for (int p = 0; p < 8; ++p) {
                    const u64 ov = *(const u64*)&kst[d * XT + tb + 2 * p];
                    a2[p][0] = f2fma(ov, wx, a2[p][0]);
                    a2[p][1] = f2fma(ov, wy, a2[p][1]);
                }
            }
            #pragma unroll
            for (int p = 0; p < 8; ++p) {
                const float2 u0 = funpack(a2[p][0]);
                const float2 u1 = funpack(a2[p][1]);
                *(u64*)&ar[(c0 + 0) * XT + tb + 2 * p] = fpack(fmaxf(u0.x, 0.f), fmaxf(u0.y, 0.f));
                *(u64*)&ar[(c0 + 1) * XT + tb + 2 * p] = fpack(fmaxf(u1.x, 0.f), fmaxf(u1.y, 0.f));
            }
        }
        __syncthreads();

        // ---- GEMM3: out_e = o1 @ Ws1 + bs1 ; accv += g * exp(out_e) ----
        {
            u64 a3[8][2];
            const float2 bb = *(const float2*)&bsh1[c0];
            #pragma unroll
            for (int p = 0; p < 8; ++p) { a3[p][0] = fdup(bb.x); a3[p][1] = fdup(bb.y); }
            u64 wn = *(const u64*)&Wsh1[c0];
            #pragma unroll 2
            for (int d = 0; d < D_; ++d) {
                const float2 w = funpack(wn);
                if (d + 1 < D_) wn = *(const u64*)&Wsh1[(d + 1) * D_ + c0];
                const u64 wx = fdup(w.x), wy = fdup(w.y);
                #pragma unroll
                for (int p = 0; p < 8; ++p) {
                    const u64 ov = *(const u64*)&ar[d * XT + tb + 2 * p];
                    a3[p][0] = f2fma(ov, wx, a3[p][0]);
                    a3[p][1] = f2fma(ov, wy, a3[p][1]);
                }
            }
            #pragma unroll
            for (int p = 0; p < 8; ++p) {
                const float2 u0 = funpack(a3[p][0]);
                const float2 u1 = funpack(a3[p][1]);
                accv[p][0][0] += g * expf(u0.x);
                accv[p][0][1] += g * expf(u0.y);
                accv[p][1][0] += g * expf(u1.x);
                accv[p][1][1] += g * expf(u1.y);
            }
        }
        __syncthreads();
    }

    // ---- combine epilogue: log(sum g*exp), EPS guard; STG.64 along cols ----
    const float EPSF = 2.2204460492503131e-16f;
    #pragma unroll
    for (int p = 0; p < 8; ++p) {
        const int t0 = tb + 2 * p;
        float v00 = accv[p][0][0]; if (v00 == 0.f) v00 = EPSF;
        float v10 = accv[p][1][0]; if (v10 == 0.f) v10 = EPSF;
        float v01 = accv[p][0][1]; if (v01 == 0.f) v01 = EPSF;
        float v11 = accv[p][1][1]; if (v11 == 0.f) v11 = EPSF;
        *(u64*)&out[(((size_t)b * T_ + t0)     * N_ + n) * D_ + c0] = fpack(logf(v00), logf(v10));
        *(u64*)&out[(((size_t)b * T_ + t0 + 1) * N_ + n) * D_ + c0] = fpack(logf(v01), logf(v11));
    }
}

// ---------------------------------------------------------------------------
// launcher
// ---------------------------------------------------------------------------
extern "C" void kernel_launch(void* const* d_in, const int* in_sizes, int n_in,
                              void* d_out, int out_size) {
    const float* x  = (const float*)d_in[0];
    const float* Wg = (const float*)d_in[1];
    const float* Wd = (const float*)d_in[2];
    const float* bd = (const float*)d_in[3];
    const float* Ws = (const float*)d_in[4];
    const float* bs = (const float*)d_in[5];
    float* out = (float*)d_out;

    const int smem_bytes = 33536 * (int)sizeof(float); // 134144 B
    cudaFuncSetAttribute(moe_kernel, cudaFuncAttributeMaxDynamicSharedMemorySize, smem_bytes);

    gate_kernel<<<B_, 128>>>(x, Wg);
    dim3 grid(N_, B_);
    moe_kernel<<<grid, 256, smem_bytes>>>(x, Wd, bd, Ws, bs, out);
}

// round 3
// speedup vs baseline: 1.5762x; 1.2112x over previous
#include <cuda_runtime.h>
#include <math.h>

#define B_ 32
#define T_ 64
#define N_ 32
#define D_ 128
#define E_ 8
#define K_ 2
#define XT 66    // stride for [feature][time] tiles (64 + pad, even for LDS.64)
#define AT 130   // stride for att_t [kt][row] tile (128 + pad, even)

typedef unsigned long long u64;

__device__ int   d_eidx[B_][K_];
__device__ float d_gateg[B_][K_];

// ---- f32x2 packed-math helpers (FFMA2 reachable only via PTX) ----
__device__ __forceinline__ u64 f2fma(u64 a, u64 b, u64 c) {
    u64 d; asm("fma.rn.f32x2 %0, %1, %2, %3;" : "=l"(d) : "l"(a), "l"(b), "l"(c)); return d;
}
__device__ __forceinline__ u64 f2mul(u64 a, u64 b) {
    u64 d; asm("mul.rn.f32x2 %0, %1, %2;" : "=l"(d) : "l"(a), "l"(b)); return d;
}
__device__ __forceinline__ u64 fpack(float lo, float hi) {
    u64 d; asm("mov.b64 %0, {%1, %2};" : "=l"(d) : "f"(lo), "f"(hi)); return d;
}
__device__ __forceinline__ u64 fdup(float v) { return fpack(v, v); }
__device__ __forceinline__ float2 funpack(u64 v) {
    float2 r; asm("mov.b64 {%0, %1}, %2;" : "=f"(r.x), "=f"(r.y) : "l"(v)); return r;
}

// ---------------------------------------------------------------------------
// Kernel 1: gating (eval mode)
// ---------------------------------------------------------------------------
__global__ void gate_kernel(const float* __restrict__ x,
                            const float* __restrict__ Wg) {
    const int b   = blockIdx.x;
    const int tid = threadIdx.x;  // 128 threads
    __shared__ float smean[D_];
    __shared__ float slog[E_];

    const float* xb = x + (size_t)b * T_ * N_ * D_;
    float s = 0.f;
    for (int i = 0; i < T_ * N_; ++i) s += xb[(size_t)i * D_ + tid];
    smean[tid] = s * (1.0f / (float)(T_ * N_));
    __syncthreads();

    if (tid < E_) {
        float l = 0.f;
        for (int d = 0; d < D_; ++d) l += smean[d] * Wg[d * E_ + tid];
        slog[tid] = l;
    }
    __syncthreads();

    if (tid == 0) {
        int i0 = 0; float v0 = slog[0];
        for (int e = 1; e < E_; ++e) if (slog[e] > v0) { v0 = slog[e]; i0 = e; }
        int i1 = -1; float v1 = -3.0e38f;
        for (int e = 0; e < E_; ++e) if (e != i0 && slog[e] > v1) { v1 = slog[e]; i1 = e; }
        const float e1  = expf(v1 - v0);
        const float inv = 1.0f / (1.0f + e1);
        d_eidx[b][0]  = i0; d_eidx[b][1]  = i1;
        d_gateg[b][0] = inv; d_gateg[b][1] = e1 * inv;
    }
}

// ---------------------------------------------------------------------------
// Kernel 2: one CTA per (b, n). 512 threads (16 warps) for latency hiding.
// SMEM: xs_t[128][66] | kst[128][66] (k_t then o_t) | vs[64][128] |
//       ar (att_t[64][130], then o1_t[128][66])  -> 33536 floats = 131 KB
// ---------------------------------------------------------------------------
__global__ __launch_bounds__(512, 1)
void moe_kernel(const float* __restrict__ x,
                const float* __restrict__ Wd,
                const float* __restrict__ bd,
                const float* __restrict__ Ws,
                const float* __restrict__ bs,
                float* __restrict__ out) {
    extern __shared__ float sm[];
    float* xs  = sm;                 // 8448 floats  [d][t] stride 66
    float* kst = sm + 8448;          // 8448 floats  [feat][t] stride 66
    float* vs  = sm + 16896;         // 8192 floats  [t][feat]
    float* ar  = sm + 25088;         // 8448 floats  att_t[kt][row]=130 / o1_t stride 66

    const int n    = blockIdx.x;
    const int b    = blockIdx.y;
    const int tid  = threadIdx.x;
    const int lane = tid & 31;
    const int wid  = tid >> 5;

    // ---- load x slab [T][D] coalesced, store transposed xs_t[d][t] ----
    {
        const float4* xg = (const float4*)(x + ((size_t)b * T_ * N_ + n) * D_);
        #pragma unroll
        for (int i = tid; i < T_ * D_ / 4; i += 512) {
            const int t  = i >> 5;
            const int c4 = i & 31;
            float4 v = xg[(size_t)t * (N_ * D_ / 4) + c4];
            const int d0 = c4 * 4;
            xs[(d0 + 0) * XT + t] = v.x;
            xs[(d0 + 1) * XT + t] = v.y;
            xs[(d0 + 2) * XT + t] = v.z;
            xs[(d0 + 3) * XT + t] = v.w;
        }
    }

    // GEMM thread mapping: column-pair cp, row-group rg (8 rows = 4 pairs)
    const int cp = tid & 63;
    const int rg = tid >> 6;        // 0..7
    const int c0 = cp * 2;
    const int tb = rg * 8;

    float accv[4][2][2];  // [row-pair][col][row-in-pair]
    #pragma unroll
    for (int p = 0; p < 4; ++p)
        for (int q = 0; q < 2; ++q) { accv[p][q][0] = 0.f; accv[p][q][1] = 0.f; }

    __syncthreads();

    for (int slot = 0; slot < K_; ++slot) {
        const int   e = d_eidx[b][slot];
        const float g = d_gateg[b][slot];
        const float* W0 = Wd + ((size_t)(e * 2 + 0) * N_ + n) * D_ * D_;
        const float* W1 = Wd + ((size_t)(e * 2 + 1) * N_ + n) * D_ * D_;
        const float* b0 = bd + ((size_t)(e * 2 + 0) * N_ + n) * D_;
        const float* b1 = bd + ((size_t)(e * 2 + 1) * N_ + n) * D_;

        // ---- GEMM1: k = x@W0+b0 (store transposed), v = x@W1+b1 ----
        {
            u64 ak[4][2], av2[4][2];
            const float2 bk = *(const float2*)&b0[c0];
            const float2 bv = *(const float2*)&b1[c0];
            #pragma unroll
            for (int p = 0; p < 4; ++p) {
                ak[p][0] = fdup(bk.x);  ak[p][1] = fdup(bk.y);
                av2[p][0] = fdup(bv.x); av2[p][1] = fdup(bv.y);
            }
            u64 w0n = *(const u64*)&W0[c0];
            u64 w1n = *(const u64*)&W1[c0];
            #pragma unroll 4
            for (int d = 0; d < D_; ++d) {
                const float2 w0 = funpack(w0n);
                const float2 w1 = funpack(w1n);
                if (d + 1 < D_) {
                    w0n = *(const u64*)&W0[(d + 1) * D_ + c0];
                    w1n = *(const u64*)&W1[(d + 1) * D_ + c0];
                }
                const u64 w0x = fdup(w0.x), w0y = fdup(w0.y);
                const u64 w1x = fdup(w1.x), w1y = fdup(w1.y);
                #pragma unroll
                for (int p = 0; p < 4; ++p) {
                    const u64 xv = *(const u64*)&xs[d * XT + tb + 2 * p];
                    ak[p][0]  = f2fma(xv, w0x, ak[p][0]);
                    ak[p][1]  = f2fma(xv, w0y, ak[p][1]);
                    av2[p][0] = f2fma(xv, w1x, av2[p][0]);
                    av2[p][1] = f2fma(xv, w1y, av2[p][1]);
                }
            }
            #pragma unroll
            for (int p = 0; p < 4; ++p) {
                *(u64*)&kst[(c0 + 0) * XT + tb + 2 * p] = ak[p][0];
                *(u64*)&kst[(c0 + 1) * XT + tb + 2 * p] = ak[p][1];
                const float2 u0 = funpack(av2[p][0]);
                const float2 u1 = funpack(av2[p][1]);
                vs[(tb + 2 * p)     * D_ + c0]     = u0.x;
                vs[(tb + 2 * p + 1) * D_ + c0]     = u0.y;
                vs[(tb + 2 * p)     * D_ + c0 + 1] = u1.x;
                vs[(tb + 2 * p + 1) * D_ + c0 + 1] = u1.y;
            }
        }
        __syncthreads();

        // ---- attention scores: att_t[kt][h*64+qt] = (q.k)/8 ----
        // thread: kt = cp, q-rows = tb..tb+7 (both heads)
        {
            u64 aa0[4], aa1[4];
            #pragma unroll
            for (int p = 0; p < 4; ++p) { aa0[p] = 0ull; aa1[p] = 0ull; }
            #pragma unroll 4
            for (int d = 0; d < 64; ++d) {
                const u64 k0 = fdup(kst[d * XT + cp]);
                const u64 k1 = fdup(kst[(64 + d) * XT + cp]);
                #pragma unroll
                for (int p = 0; p < 4; ++p) {
                    const u64 x0 = *(const u64*)&xs[d * XT + tb + 2 * p];
                    const u64 x1 = *(const u64*)&xs[(64 + d) * XT + tb + 2 * p];
                    aa0[p] = f2fma(x0, k0, aa0[p]);
                    aa1[p] = f2fma(x1, k1, aa1[p]);
                }
            }
            const u64 sc = fdup(0.125f);
            #pragma unroll
            for (int p = 0; p < 4; ++p) {
                *(u64*)&ar[cp * AT + tb + 2 * p]      = f2mul(aa0[p], sc);
                *(u64*)&ar[cp * AT + 64 + tb + 2 * p] = f2mul(aa1[p], sc);
            }
        }
        __syncthreads();

        // ---- softmax over kt: 16 warps × 8 rows ----
        for (int r = wid * 8; r < wid * 8 + 8; ++r) {
            const float a0 = ar[lane * AT + r];
            const float a1 = ar[(lane + 32) * AT + r];
            float m = fmaxf(a0, a1);
            #pragma unroll
            for (int o = 16; o > 0; o >>= 1) m = fmaxf(m, __shfl_xor_sync(0xffffffffu, m, o));
            const float e0 = expf(a0 - m);
            const float e1x = expf(a1 - m);
            float s = e0 + e1x;
            #pragma unroll
            for (int o = 16; o > 0; o >>= 1) s += __shfl_xor_sync(0xffffffffu, s, o);
            const float inv = 1.0f / s;
            ar[lane * AT + r]        = e0 * inv;
            ar[(lane + 32) * AT + r] = e1x * inv;
        }
        __syncthreads();

        // ---- oGEMM: o_t[dc][t] = sum_kt att_t[kt][hh*64+t] * v[kt][dc] ----
        {
            const int dc = tid & 127;
            const int tq = (tid >> 7) * 16;   // 4 groups of 16 rows = 8 pairs
            const int hh = dc >> 6;
            u64 ao[8];
            #pragma unroll
            for (int p = 0; p < 8; ++p) ao[p] = 0ull;
            #pragma unroll 4
            for (int ktt = 0; ktt < 64; ++ktt) {
                const u64 vv = fdup(vs[ktt * D_ + dc]);
                #pragma unroll
                for (int p = 0; p < 8; ++p) {
                    const u64 at = *(const u64*)&ar[ktt * AT + hh * 64 + tq + 2 * p];
                    ao[p] = f2fma(at, vv, ao[p]);
                }
            }
            #pragma unroll
            for (int p = 0; p < 8; ++p)
                *(u64*)&kst[dc * XT + tq + 2 * p] = ao[p];
        }
        __syncthreads();

        const float* Wsh0 = Ws + (size_t)(e * 2 + 0) * D_ * D_;
        const float* Wsh1 = Ws + (size_t)(e * 2 + 1) * D_ * D_;
        const float* bsh0 = bs + (e * 2 + 0) * D_;
        const float* bsh1 = bs + (e * 2 + 1) * D_;

        // ---- GEMM2: o1 = relu(o @ Ws0 + bs0) -> ar as o1_t ----
        {
            u64 a2[4][2];
            const float2 bb = *(const float2*)&bsh0[c0];
            #pragma unroll
            for (int p = 0; p < 4; ++p) { a2[p][0] = fdup(bb.x); a2[p][1] = fdup(bb.y); }
            u64 wn = *(const u64*)&Wsh0[c0];
            #pragma unroll 4
            for (int d = 0; d < D_; ++d) {
                const float2 w = funpack(wn);
                if (d + 1 < D_) wn = *(const u64*)&Wsh0[(d + 1) * D_ + c0];
                const u64 wx = fdup(w.x), wy = fdup(w.y);
                #pragma unroll
                for (int p = 0; p < 4; ++p) {
                    const u64 ov = *(const u64*)&kst[d * XT + tb + 2 * p];
                    a2[p][0] = f2fma(ov, wx, a2[p][0]);
                    a2[p][1] = f2fma(ov, wy, a2[p][1]);
                }
            }
            #pragma unroll
            for (int p = 0; p < 4; ++p) {
                const float2 u0 = funpack(a2[p][0]);
                const float2 u1 = funpack(a2[p][1]);
                *(u64*)&ar[(c0 + 0) * XT + tb + 2 * p] = fpack(fmaxf(u0.x, 0.f), fmaxf(u0.y, 0.f));
                *(u64*)&ar[(c0 + 1) * XT + tb + 2 * p] = fpack(fmaxf(u1.x, 0.f), fmaxf(u1.y, 0.f));
            }
        }
        __syncthreads();

        // ---- GEMM3: out_e = o1 @ Ws1 + bs1 ; accv += g * exp(out_e) ----
        {
            u64 a3[4][2];
            const float2 bb = *(const float2*)&bsh1[c0];
            #pragma unroll
            for (int p = 0; p < 4; ++p) { a3[p][0] = fdup(bb.x); a3[p][1] = fdup(bb.y); }
            u64 wn = *(const u64*)&Wsh1[c0];
            #pragma unroll 4
            for (int d = 0; d < D_; ++d) {
                const float2 w = funpack(wn);
                if (d + 1 < D_) wn = *(const u64*)&Wsh1[(d + 1) * D_ + c0];
                const u64 wx = fdup(w.x), wy = fdup(w.y);
                #pragma unroll
                for (int p = 0; p < 4; ++p) {
                    const u64 ov = *(const u64*)&ar[d * XT + tb + 2 * p];
                    a3[p][0] = f2fma(ov, wx, a3[p][0]);
                    a3[p][1] = f2fma(ov, wy, a3[p][1]);
                }
            }
            #pragma unroll
            for (int p = 0; p < 4; ++p) {
                const float2 u0 = funpack(a3[p][0]);
                const float2 u1 = funpack(a3[p][1]);
                accv[p][0][0] += g * expf(u0.x);
                accv[p][0][1] += g * expf(u0.y);
                accv[p][1][0] += g * expf(u1.x);
                accv[p][1][1] += g * expf(u1.y);
            }
        }
        __syncthreads();
    }

    // ---- combine epilogue: log(sum g*exp), EPS guard; STG.64 along cols ----
    const float EPSF = 2.2204460492503131e-16f;
    #pragma unroll
    for (int p = 0; p < 4; ++p) {
        const int t0 = tb + 2 * p;
        float v00 = accv[p][0][0]; if (v00 == 0.f) v00 = EPSF;
        float v10 = accv[p][1][0]; if (v10 == 0.f) v10 = EPSF;
        float v01 = accv[p][0][1]; if (v01 == 0.f) v01 = EPSF;
        float v11 = accv[p][1][1]; if (v11 == 0.f) v11 = EPSF;
        *(u64*)&out[(((size_t)b * T_ + t0)     * N_ + n) * D_ + c0] = fpack(logf(v00), logf(v10));
        *(u64*)&out[(((size_t)b * T_ + t0 + 1) * N_ + n) * D_ + c0] = fpack(logf(v01), logf(v11));
    }
}

// ---------------------------------------------------------------------------
// launcher
// ---------------------------------------------------------------------------
extern "C" void kernel_launch(void* const* d_in, const int* in_sizes, int n_in,
                              void* d_out, int out_size) {
    const float* x  = (const float*)d_in[0];
    const float* Wg = (const float*)d_in[1];
    const float* Wd = (const float*)d_in[2];
    const float* bd = (const float*)d_in[3];
    const float* Ws = (const float*)d_in[4];
    const float* bs = (const float*)d_in[5];
    float* out = (float*)d_out;

    const int smem_bytes = 33536 * (int)sizeof(float); // 134144 B
    cudaFuncSetAttribute(moe_kernel, cudaFuncAttributeMaxDynamicSharedMemorySize, smem_bytes);

    gate_kernel<<<B_, 128>>>(x, Wg);
    dim3 grid(N_, B_);
    moe_kernel<<<grid, 512, smem_bytes>>>(x, Wd, bd, Ws, bs, out);
}

// round 4
// speedup vs baseline: 1.8831x; 1.1947x over previous
#include <cuda_runtime.h>
#include <math.h>

#define B_ 32
#define T_ 64
#define N_ 32
#define D_ 128
#define E_ 8
#define K_ 2
#define XT 66    // stride for [feature][time] tiles (64 + pad, even for LDS.64)
#define AT 130   // stride for att_t [kt][row] tile (128 + pad, even)

typedef unsigned long long u64;

__device__ int   d_eidx[B_][K_];
__device__ float d_gateg[B_][K_];

// ---- f32x2 packed-math helpers (FFMA2 reachable only via PTX) ----
__device__ __forceinline__ u64 f2fma(u64 a, u64 b, u64 c) {
    u64 d; asm("fma.rn.f32x2 %0, %1, %2, %3;" : "=l"(d) : "l"(a), "l"(b), "l"(c)); return d;
}
__device__ __forceinline__ u64 f2mul(u64 a, u64 b) {
    u64 d; asm("mul.rn.f32x2 %0, %1, %2;" : "=l"(d) : "l"(a), "l"(b)); return d;
}
__device__ __forceinline__ u64 fpack(float lo, float hi) {
    u64 d; asm("mov.b64 %0, {%1, %2};" : "=l"(d) : "f"(lo), "f"(hi)); return d;
}
__device__ __forceinline__ u64 fdup(float v) { return fpack(v, v); }
__device__ __forceinline__ float2 funpack(u64 v) {
    float2 r; asm("mov.b64 {%0, %1}, %2;" : "=f"(r.x), "=f"(r.y) : "l"(v)); return r;
}

// ---------------------------------------------------------------------------
// Kernel 1: gating (eval mode)
// ---------------------------------------------------------------------------
__global__ void gate_kernel(const float* __restrict__ x,
                            const float* __restrict__ Wg) {
    const int b   = blockIdx.x;
    const int tid = threadIdx.x;  // 128 threads
    __shared__ float smean[D_];
    __shared__ float slog[E_];

    const float* xb = x + (size_t)b * T_ * N_ * D_;
    float s = 0.f;
    for (int i = 0; i < T_ * N_; ++i) s += xb[(size_t)i * D_ + tid];
    smean[tid] = s * (1.0f / (float)(T_ * N_));
    __syncthreads();

    if (tid < E_) {
        float l = 0.f;
        for (int d = 0; d < D_; ++d) l += smean[d] * Wg[d * E_ + tid];
        slog[tid] = l;
    }
    __syncthreads();

    if (tid == 0) {
        int i0 = 0; float v0 = slog[0];
        for (int e = 1; e < E_; ++e) if (slog[e] > v0) { v0 = slog[e]; i0 = e; }
        int i1 = -1; float v1 = -3.0e38f;
        for (int e = 0; e < E_; ++e) if (e != i0 && slog[e] > v1) { v1 = slog[e]; i1 = e; }
        const float e1  = expf(v1 - v0);
        const float inv = 1.0f / (1.0f + e1);
        d_eidx[b][0]  = i0; d_eidx[b][1]  = i1;
        d_gateg[b][0] = inv; d_gateg[b][1] = e1 * inv;
    }
}

// ---------------------------------------------------------------------------
// Kernel 2: one CTA per (b, n). 512 threads (16 warps).
// SMEM: xs_t[128][66] | kst[128][66] (k_t then o_t) | vs[64][128] |
//       ar (att_t[64][130], then o1_t[128][66])  -> 33536 floats = 131 KB
// ---------------------------------------------------------------------------
__global__ __launch_bounds__(512, 1)
void moe_kernel(const float* __restrict__ x,
                const float* __restrict__ Wd,
                const float* __restrict__ bd,
                const float* __restrict__ Ws,
                const float* __restrict__ bs,
                float* __restrict__ out) {
    extern __shared__ float sm[];
    float* xs  = sm;                 // 8448 floats  [d][t] stride 66
    float* kst = sm + 8448;          // 8448 floats  [feat][t] stride 66
    float* vs  = sm + 16896;         // 8192 floats  [t][feat]
    float* ar  = sm + 25088;         // 8448 floats  att_t[kt][row]=130 / o1_t stride 66

    const int n    = blockIdx.x;
    const int b    = blockIdx.y;
    const int tid  = threadIdx.x;
    const int lane = tid & 31;
    const int wid  = tid >> 5;

    // ---- load x slab [T][D] coalesced, store transposed xs_t[d][t] ----
    {
        const float4* xg = (const float4*)(x + ((size_t)b * T_ * N_ + n) * D_);
        #pragma unroll
        for (int i = tid; i < T_ * D_ / 4; i += 512) {
            const int t  = i >> 5;
            const int c4 = i & 31;
            float4 v = xg[(size_t)t * (N_ * D_ / 4) + c4];
            const int d0 = c4 * 4;
            xs[(d0 + 0) * XT + t] = v.x;
            xs[(d0 + 1) * XT + t] = v.y;
            xs[(d0 + 2) * XT + t] = v.z;
            xs[(d0 + 3) * XT + t] = v.w;
        }
    }

    // weight-GEMM thread mapping: column-pair cp, row-group rg (8 rows)
    const int cp = tid & 63;
    const int rg = tid >> 6;        // 0..7
    const int c0 = cp * 2;
    const int tb = rg * 8;

    float accv[4][2][2];  // [row-pair][col][row-in-pair]
    #pragma unroll
    for (int p = 0; p < 4; ++p)
        for (int q = 0; q < 2; ++q) { accv[p][q][0] = 0.f; accv[p][q][1] = 0.f; }

    __syncthreads();

    for (int slot = 0; slot < K_; ++slot) {
        const int   e = d_eidx[b][slot];
        const float g = d_gateg[b][slot];
        const float* W0 = Wd + ((size_t)(e * 2 + 0) * N_ + n) * D_ * D_;
        const float* W1 = Wd + ((size_t)(e * 2 + 1) * N_ + n) * D_ * D_;
        const float* b0 = bd + ((size_t)(e * 2 + 0) * N_ + n) * D_;
        const float* b1 = bd + ((size_t)(e * 2 + 1) * N_ + n) * D_;

        // ---- GEMM1: k = x@W0+b0 (store transposed), v = x@W1+b1 ----
        {
            u64 ak[4][2], av2[4][2];
            const float2 bk = *(const float2*)&b0[c0];
            const float2 bv = *(const float2*)&b1[c0];
            #pragma unroll
            for (int p = 0; p < 4; ++p) {
                ak[p][0] = fdup(bk.x);  ak[p][1] = fdup(bk.y);
                av2[p][0] = fdup(bv.x); av2[p][1] = fdup(bv.y);
            }
            u64 w0n = *(const u64*)&W0[c0];
            u64 w1n = *(const u64*)&W1[c0];
            #pragma unroll 4
            for (int d = 0; d < D_; ++d) {
                const float2 w0 = funpack(w0n);
                const float2 w1 = funpack(w1n);
                if (d + 1 < D_) {
                    w0n = *(const u64*)&W0[(d + 1) * D_ + c0];
                    w1n = *(const u64*)&W1[(d + 1) * D_ + c0];
                }
                const u64 w0x = fdup(w0.x), w0y = fdup(w0.y);
                const u64 w1x = fdup(w1.x), w1y = fdup(w1.y);
                #pragma unroll
                for (int p = 0; p < 4; ++p) {
                    const u64 xv = *(const u64*)&xs[d * XT + tb + 2 * p];
                    ak[p][0]  = f2fma(xv, w0x, ak[p][0]);
                    ak[p][1]  = f2fma(xv, w0y, ak[p][1]);
                    av2[p][0] = f2fma(xv, w1x, av2[p][0]);
                    av2[p][1] = f2fma(xv, w1y, av2[p][1]);
                }
            }
            #pragma unroll
            for (int p = 0; p < 4; ++p) {
                *(u64*)&kst[(c0 + 0) * XT + tb + 2 * p] = ak[p][0];
                *(u64*)&kst[(c0 + 1) * XT + tb + 2 * p] = ak[p][1];
                const float2 u0 = funpack(av2[p][0]);
                const float2 u1 = funpack(av2[p][1]);
                vs[(tb + 2 * p)     * D_ + c0]     = u0.x;
                vs[(tb + 2 * p + 1) * D_ + c0]     = u0.y;
                vs[(tb + 2 * p)     * D_ + c0 + 1] = u1.x;
                vs[(tb + 2 * p + 1) * D_ + c0 + 1] = u1.y;
            }
        }
        __syncthreads();

        // ---- attention scores (2D register tile): thread = (hh, kt-pair, 8 q-rows)
        // att_t[kt][hh*64+qt] = (q.k)/8
        {
            const int ktp = tid & 31;          // kt pair index
            const int qg  = (tid >> 5) & 7;    // q row group (8 rows)
            const int hh  = tid >> 8;          // head
            const int kt0 = ktp * 2;
            const int q0  = qg * 8;
            const int db  = hh * 64;

            u64 acc[2][4];
            #pragma unroll
            for (int i = 0; i < 2; ++i)
                for (int p = 0; p < 4; ++p) acc[i][p] = 0ull;

            #pragma unroll 4
            for (int d = 0; d < 64; ++d) {
                const float2 kk = *(const float2*)&kst[(db + d) * XT + kt0];
                const u64 kd0 = fdup(kk.x);
                const u64 kd1 = fdup(kk.y);
                #pragma unroll
                for (int p = 0; p < 4; ++p) {
                    const u64 xq = *(const u64*)&xs[(db + d) * XT + q0 + 2 * p];
                    acc[0][p] = f2fma(xq, kd0, acc[0][p]);
                    acc[1][p] = f2fma(xq, kd1, acc[1][p]);
                }
            }
            const u64 sc = fdup(0.125f);
            #pragma unroll
            for (int i = 0; i < 2; ++i)
                #pragma unroll
                for (int p = 0; p < 4; ++p)
                    *(u64*)&ar[(kt0 + i) * AT + db + q0 + 2 * p] = f2mul(acc[i][p], sc);
        }
        __syncthreads();

        // ---- softmax over kt: 16 warps × 8 rows ----
        for (int r = wid * 8; r < wid * 8 + 8; ++r) {
            const float a0 = ar[lane * AT + r];
            const float a1 = ar[(lane + 32) * AT + r];
            float m = fmaxf(a0, a1);
            #pragma unroll
            for (int o = 16; o > 0; o >>= 1) m = fmaxf(m, __shfl_xor_sync(0xffffffffu, m, o));
            const float e0 = __expf(a0 - m);
            const float e1x = __expf(a1 - m);
            float s = e0 + e1x;
            #pragma unroll
            for (int o = 16; o > 0; o >>= 1) s += __shfl_xor_sync(0xffffffffu, s, o);
            const float inv = 1.0f / s;
            ar[lane * AT + r]        = e0 * inv;
            ar[(lane + 32) * AT + r] = e1x * inv;
        }
        __syncthreads();

        // ---- oGEMM (2D register tile): thread = (dc-pair, 8 t-rows)
        // o_t[dc][t] = sum_kt att_t[kt][hh*64+t] * v[kt][dc]
        {
            const int dcp = tid & 63;
            const int tg  = tid >> 6;        // 0..7
            const int dc0 = dcp * 2;
            const int t0  = tg * 8;
            const int hh  = dcp >> 5;        // warp-uniform
            const int rb  = hh * 64 + t0;

            u64 acc[2][4];
            #pragma unroll
            for (int i = 0; i < 2; ++i)
                for (int p = 0; p < 4; ++p) acc[i][p] = 0ull;

            #pragma unroll 4
            for (int kt = 0; kt < 64; ++kt) {
                const float2 vv = *(const float2*)&vs[kt * D_ + dc0];
                const u64 v0 = fdup(vv.x);
                const u64 v1 = fdup(vv.y);
                #pragma unroll
                for (int p = 0; p < 4; ++p) {
                    const u64 at = *(const u64*)&ar[kt * AT + rb + 2 * p];
                    acc[0][p] = f2fma(at, v0, acc[0][p]);
                    acc[1][p] = f2fma(at, v1, acc[1][p]);
                }
            }
            #pragma unroll
            for (int i = 0; i < 2; ++i)
                #pragma unroll
                for (int p = 0; p < 4; ++p)
                    *(u64*)&kst[(dc0 + i) * XT + t0 + 2 * p] = acc[i][p];
        }
        __syncthreads();

        const float* Wsh0 = Ws + (size_t)(e * 2 + 0) * D_ * D_;
        const float* Wsh1 = Ws + (size_t)(e * 2 + 1) * D_ * D_;
        const float* bsh0 = bs + (e * 2 + 0) * D_;
        const float* bsh1 = bs + (e * 2 + 1) * D_;

        // ---- GEMM2: o1 = relu(o @ Ws0 + bs0) -> ar as o1_t ----
        {
            u64 a2[4][2];
            const float2 bb = *(const float2*)&bsh0[c0];
            #pragma unroll
            for (int p = 0; p < 4; ++p) { a2[p][0] = fdup(bb.x); a2[p][1] = fdup(bb.y); }
            u64 wn = *(const u64*)&Wsh0[c0];
            #pragma unroll 4
            for (int d = 0; d < D_; ++d) {
                const float2 w = funpack(wn);
                if (d + 1 < D_) wn = *(const u64*)&Wsh0[(d + 1) * D_ + c0];
                const u64 wx = fdup(w.x), wy = fdup(w.y);
                #pragma unroll
                for (int p = 0; p < 4; ++p) {
                    const u64 ov = *(const u64*)&kst[d * XT + tb + 2 * p];
                    a2[p][0] = f2fma(ov, wx, a2[p][0]);
                    a2[p][1] = f2fma(ov, wy, a2[p][1]);
                }
            }
            #pragma unroll
            for (int p = 0; p < 4; ++p) {
                const float2 u0 = funpack(a2[p][0]);
                const float2 u1 = funpack(a2[p][1]);
                *(u64*)&ar[(c0 + 0) * XT + tb + 2 * p] = fpack(fmaxf(u0.x, 0.f), fmaxf(u0.y, 0.f));
                *(u64*)&ar[(c0 + 1) * XT + tb + 2 * p] = fpack(fmaxf(u1.x, 0.f), fmaxf(u1.y, 0.f));
            }
        }
        __syncthreads();

        // ---- GEMM3: out_e = o1 @ Ws1 + bs1 ; accv += g * exp(out_e) ----
        {
            u64 a3[4][2];
            const float2 bb = *(const float2*)&bsh1[c0];
            #pragma unroll
            for (int p = 0; p < 4; ++p) { a3[p][0] = fdup(bb.x); a3[p][1] = fdup(bb.y); }
            u64 wn = *(const u64*)&Wsh1[c0];
            #pragma unroll 4
            for (int d = 0; d < D_; ++d) {
                const float2 w = funpack(wn);
                if (d + 1 < D_) wn = *(const u64*)&Wsh1[(d + 1) * D_ + c0];
                const u64 wx = fdup(w.x), wy = fdup(w.y);
                #pragma unroll
                for (int p = 0; p < 4; ++p) {
                    const u64 ov = *(const u64*)&ar[d * XT + tb + 2 * p];
                    a3[p][0] = f2fma(ov, wx, a3[p][0]);
                    a3[p][1] = f2fma(ov, wy, a3[p][1]);
                }
            }
            #pragma unroll
            for (int p = 0; p < 4; ++p) {
                const float2 u0 = funpack(a3[p][0]);
                const float2 u1 = funpack(a3[p][1]);
                accv[p][0][0] += g * __expf(u0.x);
                accv[p][0][1] += g * __expf(u0.y);
                accv[p][1][0] += g * __expf(u1.x);
                accv[p][1][1] += g * __expf(u1.y);
            }
        }
        __syncthreads();
    }

    // ---- combine epilogue: log(sum g*exp), EPS guard; STG.64 along cols ----
    const float EPSF = 2.2204460492503131e-16f;
    #pragma unroll
    for (int p = 0; p < 4; ++p) {
        const int t0 = tb + 2 * p;
        float v00 = accv[p][0][0]; if (v00 == 0.f) v00 = EPSF;
        float v10 = accv[p][1][0]; if (v10 == 0.f) v10 = EPSF;
        float v01 = accv[p][0][1]; if (v01 == 0.f) v01 = EPSF;
        float v11 = accv[p][1][1]; if (v11 == 0.f) v11 = EPSF;
        *(u64*)&out[(((size_t)b * T_ + t0)     * N_ + n) * D_ + c0] = fpack(__logf(v00), __logf(v10));
        *(u64*)&out[(((size_t)b * T_ + t0 + 1) * N_ + n) * D_ + c0] = fpack(__logf(v01), __logf(v11));
    }
}

// ---------------------------------------------------------------------------
// launcher
// ---------------------------------------------------------------------------
extern "C" void kernel_launch(void* const* d_in, const int* in_sizes, int n_in,
                              void* d_out, int out_size) {
    const float* x  = (const float*)d_in[0];
    const float* Wg = (const float*)d_in[1];
    const float* Wd = (const float*)d_in[2];
    const float* bd = (const float*)d_in[3];
    const float* Ws = (const float*)d_in[4];
    const float* bs = (const float*)d_in[5];
    float* out = (float*)d_out;

    const int smem_bytes = 33536 * (int)sizeof(float); // 134144 B
    cudaFuncSetAttribute(moe_kernel, cudaFuncAttributeMaxDynamicSharedMemorySize, smem_bytes);

    gate_kernel<<<B_, 128>>>(x, Wg);
    dim3 grid(N_, B_);
    moe_kernel<<<grid, 512, smem_bytes>>>(x, Wd, bd, Ws, bs, out);
}